// round 2
// baseline (speedup 1.0000x reference)
#include <cuda_runtime.h>
#include <math.h>

#define BB 4
#define SSZ 1024
#define DDIM 1024
#define NH 16
#define HD 64
#define FF 2048
#define HID 4096
#define MTOT (BB*SSZ)   // 4096

// ---------------- scratch (static device globals; no allocation) ----------------
__device__ float g_q[MTOT*DDIM];
__device__ float g_k[MTOT*DDIM];
__device__ float g_v[MTOT*DDIM];
__device__ float g_sc[67108864];          // [B*NH, S, S] = 256 MB
__device__ float g_attn[MTOT*DDIM];
__device__ float g_tmp[MTOT*DDIM];
__device__ float g_h[MTOT*DDIM];
__device__ float g_ffn[MTOT*FF];
__device__ float g_feat[MTOT*DDIM];
__device__ float g_feat2[MTOT*DDIM];
__device__ float g_sv[MTOT];
__device__ float g_kb2[MTOT];
__device__ int   g_seg[MTOT];
__device__ float g_pool[MTOT*DDIM];
__device__ float g_ph[16777216];          // [MTOT, HID]

// ---------------- helpers ----------------
__device__ __forceinline__ float gelu_exact(float x) {
    return 0.5f * x * (1.0f + erff(x * 0.70710678118654752440f));
}

__device__ __forceinline__ float blk_sum(float v) {
    __shared__ float sh[8];
    int lane = threadIdx.x & 31, w = threadIdx.x >> 5;
    #pragma unroll
    for (int o = 16; o; o >>= 1) v += __shfl_xor_sync(0xffffffffu, v, o);
    if (lane == 0) sh[w] = v;
    __syncthreads();
    if (threadIdx.x < 32) {
        float t = (lane < 8) ? sh[lane] : 0.0f;
        #pragma unroll
        for (int o = 4; o; o >>= 1) t += __shfl_xor_sync(0xffffffffu, t, o);
        if (lane == 0) sh[0] = t;
    }
    __syncthreads();
    float r = sh[0];
    __syncthreads();
    return r;
}

__device__ __forceinline__ float blk_max(float v) {
    __shared__ float sh[8];
    int lane = threadIdx.x & 31, w = threadIdx.x >> 5;
    #pragma unroll
    for (int o = 16; o; o >>= 1) v = fmaxf(v, __shfl_xor_sync(0xffffffffu, v, o));
    if (lane == 0) sh[w] = v;
    __syncthreads();
    if (threadIdx.x < 32) {
        float t = (lane < 8) ? sh[lane] : -3.4e38f;
        #pragma unroll
        for (int o = 4; o; o >>= 1) t = fmaxf(t, __shfl_xor_sync(0xffffffffu, t, o));
        if (lane == 0) sh[0] = t;
    }
    __syncthreads();
    float r = sh[0];
    __syncthreads();
    return r;
}

// ---------------- generic NN GEMM: C[M,N] = act(A[M,K] @ B[K,N] + bias[N]) ------
// M%128==0, N%128==0, K%8==0. 256 threads, 128x128 tile, 8x8 per thread.
template<int ACT>
__global__ void gemm128(const float* __restrict__ A, const float* __restrict__ B,
                        const float* __restrict__ bias, float* __restrict__ C,
                        int M, int N, int K) {
    __shared__ float As[8][128];
    __shared__ float Bs[8][128];
    int tid = threadIdx.x;
    int col0 = blockIdx.x * 128, row0 = blockIdx.y * 128;
    int tx = tid & 15, ty = tid >> 4;
    int ar = tid >> 1, ac = (tid & 1) * 4;         // A tile loader: 128 rows x 8 k
    int br = tid >> 5, bc = (tid & 31) * 4;        // B tile loader: 8 k x 128 cols
    const float* Aptr = A + (size_t)(row0 + ar) * K + ac;
    const float* Bptr = B + (size_t)br * N + col0 + bc;
    float acc[8][8];
    #pragma unroll
    for (int i = 0; i < 8; i++)
        #pragma unroll
        for (int j = 0; j < 8; j++) acc[i][j] = 0.0f;

    for (int k0 = 0; k0 < K; k0 += 8) {
        float4 av = *(const float4*)Aptr;
        As[ac + 0][ar] = av.x; As[ac + 1][ar] = av.y;
        As[ac + 2][ar] = av.z; As[ac + 3][ar] = av.w;
        float4 bv = *(const float4*)Bptr;
        *(float4*)&Bs[br][bc] = bv;
        __syncthreads();
        #pragma unroll
        for (int kk = 0; kk < 8; kk++) {
            float af[8], bf[8];
            #pragma unroll
            for (int i = 0; i < 8; i++) af[i] = As[kk][ty * 8 + i];
            #pragma unroll
            for (int j = 0; j < 8; j++) bf[j] = Bs[kk][tx * 8 + j];
            #pragma unroll
            for (int i = 0; i < 8; i++)
                #pragma unroll
                for (int j = 0; j < 8; j++)
                    acc[i][j] = fmaf(af[i], bf[j], acc[i][j]);
        }
        __syncthreads();
        Aptr += 8;
        Bptr += (size_t)8 * N;
    }
    #pragma unroll
    for (int i = 0; i < 8; i++) {
        int r = row0 + ty * 8 + i;
        #pragma unroll
        for (int j = 0; j < 8; j++) {
            int c = col0 + tx * 8 + j;
            float v = acc[i][j] + bias[c];
            if (ACT == 1) v = gelu_exact(v);
            C[(size_t)r * N + c] = v;
        }
    }
}

// ---------------- attention: scores[z,q,k] = 0.125 * q_h . k_h ----------------
// grid (S/64, S/64, B*NH), 256 threads, 64x64 tile, full K=64.
__global__ void attn_scores(const float* __restrict__ q, const float* __restrict__ k,
                            float* __restrict__ sc) {
    int z = blockIdx.z, b = z / NH, h = z % NH;
    int k0 = blockIdx.x * 64, q0 = blockIdx.y * 64;
    __shared__ float qs[64][65];   // [kk][qrow]
    __shared__ float ks[64][65];   // [kk][kcol]
    int tid = threadIdx.x;
    int r = tid >> 2;
    int cbase = (tid & 3) * 16;
    const float* qp = q + (size_t)(b * SSZ + q0 + r) * DDIM + h * HD + cbase;
    const float* kp = k + (size_t)(b * SSZ + k0 + r) * DDIM + h * HD + cbase;
    #pragma unroll
    for (int u = 0; u < 4; u++) {
        float4 v4 = *(const float4*)(qp + u * 4);
        qs[cbase + u * 4 + 0][r] = v4.x; qs[cbase + u * 4 + 1][r] = v4.y;
        qs[cbase + u * 4 + 2][r] = v4.z; qs[cbase + u * 4 + 3][r] = v4.w;
        float4 w4 = *(const float4*)(kp + u * 4);
        ks[cbase + u * 4 + 0][r] = w4.x; ks[cbase + u * 4 + 1][r] = w4.y;
        ks[cbase + u * 4 + 2][r] = w4.z; ks[cbase + u * 4 + 3][r] = w4.w;
    }
    __syncthreads();
    int tx = tid & 15, ty = tid >> 4;
    float acc[4][4];
    #pragma unroll
    for (int i = 0; i < 4; i++)
        #pragma unroll
        for (int j = 0; j < 4; j++) acc[i][j] = 0.0f;
    #pragma unroll 8
    for (int kk = 0; kk < 64; kk++) {
        float a[4], bv[4];
        #pragma unroll
        for (int i = 0; i < 4; i++) a[i] = qs[kk][ty * 4 + i];
        #pragma unroll
        for (int j = 0; j < 4; j++) bv[j] = ks[kk][tx * 4 + j];
        #pragma unroll
        for (int i = 0; i < 4; i++)
            #pragma unroll
            for (int j = 0; j < 4; j++)
                acc[i][j] = fmaf(a[i], bv[j], acc[i][j]);
    }
    float* out = sc + (size_t)z * SSZ * SSZ;
    #pragma unroll
    for (int i = 0; i < 4; i++)
        #pragma unroll
        for (int j = 0; j < 4; j++)
            out[(size_t)(q0 + ty * 4 + i) * SSZ + k0 + tx * 4 + j] = acc[i][j] * 0.125f;
}

// ---------------- softmax over keys with per-(b,key) bias ----------------
__global__ void softmax_rows(float* __restrict__ sc, const float* __restrict__ kb) {
    int row = blockIdx.x;                 // B*NH*S rows
    int b = row / (NH * SSZ);
    float* p = sc + (size_t)row * SSZ;
    const float* kbp = kb + b * SSZ;
    int tid = threadIdx.x;
    float v[4]; float mx = -3.4e38f;
    #pragma unroll
    for (int u = 0; u < 4; u++) {
        int c = u * 256 + tid;
        v[u] = p[c] + kbp[c];
        mx = fmaxf(mx, v[u]);
    }
    mx = blk_max(mx);
    float s = 0.0f;
    #pragma unroll
    for (int u = 0; u < 4; u++) { v[u] = expf(v[u] - mx); s += v[u]; }
    s = blk_sum(s);
    float inv = 1.0f / s;
    #pragma unroll
    for (int u = 0; u < 4; u++) p[u * 256 + tid] = v[u] * inv;
}

// ---------------- AV: attn[b,q,h*64+n] = probs[z] @ v_head ----------------
// grid (S/64, B*NH), 256 threads, 64 (q) x 64 (full head) tile, BK=16.
__global__ void attn_av(const float* __restrict__ sc, const float* __restrict__ v,
                        float* __restrict__ o) {
    int z = blockIdx.y, b = z / NH, h = z % NH;
    int q0 = blockIdx.x * 64;
    __shared__ float As[16][65];   // [kk][qrow]
    __shared__ float Bs[16][64];   // [kk][n]
    const float* Ab = sc + (size_t)z * SSZ * SSZ;
    const float* Vb = v + (size_t)b * SSZ * DDIM + h * HD;
    int tid = threadIdx.x;
    int ar = tid >> 2, ac = (tid & 3) * 4;    // 64 rows x 16 k
    int br = tid >> 4, bc = (tid & 15) * 4;   // 16 k x 64 n
    int tx = tid & 15, ty = tid >> 4;
    float acc[4][4];
    #pragma unroll
    for (int i = 0; i < 4; i++)
        #pragma unroll
        for (int j = 0; j < 4; j++) acc[i][j] = 0.0f;
    for (int k0 = 0; k0 < SSZ; k0 += 16) {
        float4 a4 = *(const float4*)(Ab + (size_t)(q0 + ar) * SSZ + k0 + ac);
        As[ac + 0][ar] = a4.x; As[ac + 1][ar] = a4.y;
        As[ac + 2][ar] = a4.z; As[ac + 3][ar] = a4.w;
        float4 b4 = *(const float4*)(Vb + (size_t)(k0 + br) * DDIM + bc);
        *(float4*)&Bs[br][bc] = b4;
        __syncthreads();
        #pragma unroll
        for (int kk = 0; kk < 16; kk++) {
            float a[4], bf[4];
            #pragma unroll
            for (int i = 0; i < 4; i++) a[i] = As[kk][ty * 4 + i];
            #pragma unroll
            for (int j = 0; j < 4; j++) bf[j] = Bs[kk][tx * 4 + j];
            #pragma unroll
            for (int i = 0; i < 4; i++)
                #pragma unroll
                for (int j = 0; j < 4; j++)
                    acc[i][j] = fmaf(a[i], bf[j], acc[i][j]);
        }
        __syncthreads();
    }
    float* Ob = o + (size_t)(b * SSZ + q0) * DDIM + h * HD;
    #pragma unroll
    for (int i = 0; i < 4; i++)
        #pragma unroll
        for (int j = 0; j < 4; j++)
            Ob[(size_t)(ty * 4 + i) * DDIM + tx * 4 + j] = acc[i][j];
}

// ---------------- residual add + LayerNorm ----------------
__global__ void add_ln(const float* __restrict__ x, const float* __restrict__ y,
                       const float* __restrict__ g, const float* __restrict__ be,
                       float* __restrict__ out) {
    int row = blockIdx.x, tid = threadIdx.x;
    const float* xp = x + (size_t)row * DDIM;
    const float* yp = y + (size_t)row * DDIM;
    float v[4]; float s = 0.0f;
    #pragma unroll
    for (int u = 0; u < 4; u++) {
        int c = u * 256 + tid;
        v[u] = xp[c] + yp[c];
        s += v[u];
    }
    s = blk_sum(s);
    float mean = s * (1.0f / DDIM);
    float qv = 0.0f;
    #pragma unroll
    for (int u = 0; u < 4; u++) { float d = v[u] - mean; qv += d * d; }
    qv = blk_sum(qv);
    float rstd = rsqrtf(qv * (1.0f / DDIM) + 1e-5f);
    float* op = out + (size_t)row * DDIM;
    #pragma unroll
    for (int u = 0; u < 4; u++) {
        int c = u * 256 + tid;
        op[c] = (v[u] - mean) * rstd * g[c] + be[c];
    }
}

// ---------------- importance score head: sv = valid ? sigmoid(f.Ws + bs) : 0 ----
__global__ void score_head(const float* __restrict__ f, const float* __restrict__ Ws,
                           const float* __restrict__ bsc, const float* __restrict__ masks,
                           float* __restrict__ sv) {
    int row = blockIdx.x, tid = threadIdx.x;
    const float* fp = f + (size_t)row * DDIM;
    float s = 0.0f;
    #pragma unroll
    for (int u = 0; u < 4; u++) {
        int c = u * 256 + tid;
        s += fp[c] * Ws[c];
    }
    s = blk_sum(s);
    if (tid == 0) {
        float val = 1.0f / (1.0f + expf(-(s + bsc[0])));
        sv[row] = (masks[row] > 0.0f) ? val : 0.0f;
    }
}

__global__ void make_kb2(const float* __restrict__ masks, float* __restrict__ kb2) {
    int i = blockIdx.x * 256 + threadIdx.x;
    if (i < MTOT) kb2[i] = (masks[i] > 0.0f) ? 0.0f : -1e9f;
}

// ---------------- sequential scan per batch (matches fp32 cumsum order) --------
__global__ void scan_kernel(const float* __restrict__ sv, const float* __restrict__ masks,
                            int* __restrict__ seg, float* __restrict__ mask_out) {
    int b = threadIdx.x;
    if (b >= BB) return;
    float c = 0.0f, maxseg = -1.0f;
    for (int t = 0; t < SSZ; t++) {
        c = c + sv[b * SSZ + t];
        float cf = floorf(c);
        int sg = (int)cf;
        if (sg > SSZ - 1) sg = SSZ - 1;
        if (sg < 0) sg = 0;
        seg[b * SSZ + t] = sg;
        if (masks[b * SSZ + t] > 0.0f) maxseg = fmaxf(maxseg, cf);
    }
    for (int t = 0; t < SSZ; t++)
        mask_out[b * SSZ + t] = ((float)t <= maxseg) ? 1.0f : 0.0f;
}

__global__ void zero_pool(float* __restrict__ p) {
    size_t i = (size_t)blockIdx.x * 256 + threadIdx.x;
    if (i < (size_t)MTOT * DDIM) p[i] = 0.0f;
}

// seg is nondecreasing -> contiguous runs; one thread per (b, d) column.
__global__ void seg_pool(const float* __restrict__ x, const float* __restrict__ sv,
                         const int* __restrict__ seg, float* __restrict__ pooled) {
    int b = blockIdx.y;
    int d = blockIdx.x * 256 + threadIdx.x;
    __shared__ float svs[SSZ];
    __shared__ int sgs[SSZ];
    for (int t = threadIdx.x; t < SSZ; t += 256) {
        svs[t] = sv[b * SSZ + t];
        sgs[t] = seg[b * SSZ + t];
    }
    __syncthreads();
    const float* xb = x + (size_t)b * SSZ * DDIM + d;
    float acc = 0.0f;
    int cur = sgs[0];
    for (int t = 0; t < SSZ; t++) {
        int sg = sgs[t];
        if (sg != cur) {
            pooled[((size_t)b * SSZ + cur) * DDIM + d] = acc;
            acc = 0.0f;
            cur = sg;
        }
        acc = fmaf(xb[(size_t)t * DDIM], svs[t], acc);
    }
    pooled[((size_t)b * SSZ + cur) * DDIM + d] = acc;
}

// ---------------- host ----------------
extern "C" void kernel_launch(void* const* d_in, const int* in_sizes, int n_in,
                              void* d_out, int out_size) {
    const float* x     = (const float*)d_in[0];
    const float* masks = (const float*)d_in[1];
    const float* Wq = (const float*)d_in[2];  const float* bq = (const float*)d_in[3];
    const float* Wk = (const float*)d_in[4];  const float* bk = (const float*)d_in[5];
    const float* Wv = (const float*)d_in[6];  const float* bv = (const float*)d_in[7];
    const float* Wo = (const float*)d_in[8];  const float* bo = (const float*)d_in[9];
    const float* g1 = (const float*)d_in[10]; const float* be1 = (const float*)d_in[11];
    const float* g2 = (const float*)d_in[12]; const float* be2 = (const float*)d_in[13];
    const float* W1 = (const float*)d_in[14]; const float* bf1 = (const float*)d_in[15];
    const float* W2 = (const float*)d_in[16]; const float* bf2 = (const float*)d_in[17];
    const float* Ws = (const float*)d_in[18]; const float* bs = (const float*)d_in[19];
    const float* P1 = (const float*)d_in[20]; const float* bp1 = (const float*)d_in[21];
    const float* P2 = (const float*)d_in[22]; const float* bp2 = (const float*)d_in[23];
    float* out = (float*)d_out;

    float *q, *k, *v, *sc, *attn, *tmp, *h, *ffn, *feat, *feat2, *sv, *kb2, *pool, *ph;
    int* seg;
    cudaGetSymbolAddress((void**)&q, g_q);
    cudaGetSymbolAddress((void**)&k, g_k);
    cudaGetSymbolAddress((void**)&v, g_v);
    cudaGetSymbolAddress((void**)&sc, g_sc);
    cudaGetSymbolAddress((void**)&attn, g_attn);
    cudaGetSymbolAddress((void**)&tmp, g_tmp);
    cudaGetSymbolAddress((void**)&h, g_h);
    cudaGetSymbolAddress((void**)&ffn, g_ffn);
    cudaGetSymbolAddress((void**)&feat, g_feat);
    cudaGetSymbolAddress((void**)&feat2, g_feat2);
    cudaGetSymbolAddress((void**)&sv, g_sv);
    cudaGetSymbolAddress((void**)&kb2, g_kb2);
    cudaGetSymbolAddress((void**)&seg, g_seg);
    cudaGetSymbolAddress((void**)&pool, g_pool);
    cudaGetSymbolAddress((void**)&ph, g_ph);

    dim3 gDD(DDIM / 128, MTOT / 128);

    auto layer = [&](const float* in, const float* kb, float* outf) {
        gemm128<0><<<gDD, 256>>>(in, Wq, bq, q, MTOT, DDIM, DDIM);
        gemm128<0><<<gDD, 256>>>(in, Wk, bk, k, MTOT, DDIM, DDIM);
        gemm128<0><<<gDD, 256>>>(in, Wv, bv, v, MTOT, DDIM, DDIM);
        dim3 gs(SSZ / 64, SSZ / 64, BB * NH);
        attn_scores<<<gs, 256>>>(q, k, sc);
        softmax_rows<<<BB * NH * SSZ, 256>>>(sc, kb);
        dim3 ga(SSZ / 64, BB * NH);
        attn_av<<<ga, 256>>>(sc, v, attn);
        gemm128<0><<<gDD, 256>>>(attn, Wo, bo, tmp, MTOT, DDIM, DDIM);
        add_ln<<<MTOT, 256>>>(in, tmp, g1, be1, h);
        gemm128<1><<<dim3(FF / 128, MTOT / 128), 256>>>(h, W1, bf1, ffn, MTOT, FF, DDIM);
        gemm128<0><<<gDD, 256>>>(ffn, W2, bf2, tmp, MTOT, DDIM, FF);
        add_ln<<<MTOT, 256>>>(h, tmp, g2, be2, outf);
    };

    layer(x, masks, feat);
    make_kb2<<<MTOT / 256, 256>>>(masks, kb2);
    layer(feat, kb2, feat2);

    score_head<<<MTOT, 256>>>(feat2, Ws, bs, masks, sv);
    scan_kernel<<<1, 32>>>(sv, masks, seg, out + (size_t)MTOT * HID);
    zero_pool<<<(MTOT * DDIM) / 256, 256>>>(pool);
    seg_pool<<<dim3(DDIM / 256, BB), 256>>>(x, sv, seg, pool);

    gemm128<1><<<dim3(HID / 128, MTOT / 128), 256>>>(pool, P1, bp1, ph, MTOT, HID, DDIM);
    gemm128<0><<<dim3(HID / 128, MTOT / 128), 256>>>(ph, P2, bp2, out, MTOT, HID, HID);
}

// round 4
// speedup vs baseline: 1.4998x; 1.4998x over previous
#include <cuda_runtime.h>
#include <cuda_bf16.h>
#include <math.h>

#define BB 4
#define SSZ 1024
#define DDIM 1024
#define NH 16
#define HD 64
#define FF 2048
#define HID 4096
#define MTOT (BB*SSZ)   // 4096

// ---------------- scratch (static device globals; no allocation) ----------------
__device__ float g_q[MTOT*DDIM];
__device__ float g_k[MTOT*DDIM];
__device__ float g_v[MTOT*DDIM];
__device__ float g_sc[67108864];          // [B*NH, S, S]
__device__ float g_attn[MTOT*DDIM];
__device__ float g_tmp[MTOT*DDIM];
__device__ float g_h[MTOT*DDIM];
__device__ float g_ffn[MTOT*FF];
__device__ float g_feat[MTOT*DDIM];
__device__ float g_feat2[MTOT*DDIM];
__device__ float g_sv[MTOT];
__device__ float g_kb2[MTOT];
__device__ int   g_seg[MTOT];
__device__ float g_pool[MTOT*DDIM];
__device__ float g_ph[16777216];          // [MTOT, HID]

// ---------------- helpers ----------------
__device__ __forceinline__ float gelu_exact(float x) {
    return 0.5f * x * (1.0f + erff(x * 0.70710678118654752440f));
}

__device__ __forceinline__ float blk_sum(float v) {
    __shared__ float sh[8];
    int lane = threadIdx.x & 31, w = threadIdx.x >> 5;
    #pragma unroll
    for (int o = 16; o; o >>= 1) v += __shfl_xor_sync(0xffffffffu, v, o);
    if (lane == 0) sh[w] = v;
    __syncthreads();
    if (threadIdx.x < 32) {
        float t = (lane < 8) ? sh[lane] : 0.0f;
        #pragma unroll
        for (int o = 4; o; o >>= 1) t += __shfl_xor_sync(0xffffffffu, t, o);
        if (lane == 0) sh[0] = t;
    }
    __syncthreads();
    float r = sh[0];
    __syncthreads();
    return r;
}

__device__ __forceinline__ float blk_max(float v) {
    __shared__ float sh[8];
    int lane = threadIdx.x & 31, w = threadIdx.x >> 5;
    #pragma unroll
    for (int o = 16; o; o >>= 1) v = fmaxf(v, __shfl_xor_sync(0xffffffffu, v, o));
    if (lane == 0) sh[w] = v;
    __syncthreads();
    if (threadIdx.x < 32) {
        float t = (lane < 8) ? sh[lane] : -3.4e38f;
        #pragma unroll
        for (int o = 4; o; o >>= 1) t = fmaxf(t, __shfl_xor_sync(0xffffffffu, t, o));
        if (lane == 0) sh[0] = t;
    }
    __syncthreads();
    float r = sh[0];
    __syncthreads();
    return r;
}

// ---------------- fp32 GEMM (double-buffered; fmaf order identical to R2) -----
// C[M,N] = act(A[M,K] @ B[K,N] + bias[N]); M%128==0, N%128==0, K%8==0.
template<int ACT>
__global__ void __launch_bounds__(256, 2)
gemm128(const float* __restrict__ A, const float* __restrict__ B,
        const float* __restrict__ bias, float* __restrict__ C,
        int M, int N, int K) {
    __shared__ float As[2][8][128];
    __shared__ float Bs[2][8][128];
    int tid = threadIdx.x;
    int col0 = blockIdx.x * 128, row0 = blockIdx.y * 128;
    int tx = tid & 15, ty = tid >> 4;
    int ar = tid >> 1, ac = (tid & 1) * 4;         // A tile loader: 128 rows x 8 k
    int br = tid >> 5, bc = (tid & 31) * 4;        // B tile loader: 8 k x 128 cols
    const float* Aptr = A + (size_t)(row0 + ar) * K + ac;
    const float* Bptr = B + (size_t)br * N + col0 + bc;
    float acc[8][8];
    #pragma unroll
    for (int i = 0; i < 8; i++)
        #pragma unroll
        for (int j = 0; j < 8; j++) acc[i][j] = 0.0f;

    // preload k0 = 0
    {
        float4 av = *(const float4*)Aptr;
        As[0][ac + 0][ar] = av.x; As[0][ac + 1][ar] = av.y;
        As[0][ac + 2][ar] = av.z; As[0][ac + 3][ar] = av.w;
        float4 bv = *(const float4*)Bptr;
        *(float4*)&Bs[0][br][bc] = bv;
    }
    __syncthreads();

    int cur = 0;
    for (int k0 = 0; k0 < K; k0 += 8) {
        bool has = (k0 + 8 < K);
        float4 av2, bv2;
        if (has) {
            av2 = *(const float4*)(Aptr + k0 + 8);
            bv2 = *(const float4*)(Bptr + (size_t)(k0 + 8) * N);
        }
        #pragma unroll
        for (int kk = 0; kk < 8; kk++) {
            float af[8], bf[8];
            #pragma unroll
            for (int i = 0; i < 8; i++) af[i] = As[cur][kk][ty * 8 + i];
            #pragma unroll
            for (int j = 0; j < 8; j++) bf[j] = Bs[cur][kk][tx * 8 + j];
            #pragma unroll
            for (int i = 0; i < 8; i++)
                #pragma unroll
                for (int j = 0; j < 8; j++)
                    acc[i][j] = fmaf(af[i], bf[j], acc[i][j]);
        }
        if (has) {
            int nb = cur ^ 1;
            As[nb][ac + 0][ar] = av2.x; As[nb][ac + 1][ar] = av2.y;
            As[nb][ac + 2][ar] = av2.z; As[nb][ac + 3][ar] = av2.w;
            *(float4*)&Bs[nb][br][bc] = bv2;
        }
        __syncthreads();
        cur ^= 1;
    }
    #pragma unroll
    for (int i = 0; i < 8; i++) {
        int r = row0 + ty * 8 + i;
        #pragma unroll
        for (int j = 0; j < 8; j++) {
            int c = col0 + tx * 8 + j;
            float v = acc[i][j] + bias[c];
            if (ACT == 1) v = gelu_exact(v);
            C[(size_t)r * N + c] = v;
        }
    }
}

// ================= bf16 split-precision tensor-core GEMM (projector only) =====
#define GA_PAD 40    // bf16 per A row (32 + 8)
#define GB_PAD 136   // bf16 per B row (128 + 8)
#define GA_SZ (128*GA_PAD)
#define GB_SZ (32*GB_PAD)

__device__ __forceinline__ void mma16816(float* d, const unsigned* a,
                                         unsigned b0, unsigned b1) {
    asm volatile(
        "mma.sync.aligned.m16n8k16.row.col.f32.bf16.bf16.f32 "
        "{%0,%1,%2,%3}, {%4,%5,%6,%7}, {%8,%9}, {%0,%1,%2,%3};"
        : "+f"(d[0]), "+f"(d[1]), "+f"(d[2]), "+f"(d[3])
        : "r"(a[0]), "r"(a[1]), "r"(a[2]), "r"(a[3]), "r"(b0), "r"(b1));
}

__device__ __forceinline__ void ldsm4(unsigned* r, const __nv_bfloat16* p) {
    unsigned addr = (unsigned)__cvta_generic_to_shared(p);
    asm volatile("ldmatrix.sync.aligned.m8n8.x4.shared.b16 {%0,%1,%2,%3}, [%4];"
                 : "=r"(r[0]), "=r"(r[1]), "=r"(r[2]), "=r"(r[3]) : "r"(addr));
}

__device__ __forceinline__ void ldsm4t(unsigned* r, const __nv_bfloat16* p) {
    unsigned addr = (unsigned)__cvta_generic_to_shared(p);
    asm volatile("ldmatrix.sync.aligned.m8n8.x4.trans.shared.b16 {%0,%1,%2,%3}, [%4];"
                 : "=r"(r[0]), "=r"(r[1]), "=r"(r[2]), "=r"(r[3]) : "r"(addr));
}

template<int SPLITS, int ACT>
__global__ void __launch_bounds__(256, 2)
gemm_mma(const float* __restrict__ A, const float* __restrict__ B,
         const float* __restrict__ bias, float* __restrict__ C,
         int M, int N, int K) {
    extern __shared__ __nv_bfloat16 smbuf[];
    __nv_bfloat16* Ah = smbuf;                       // [SPLITS][128][GA_PAD]
    __nv_bfloat16* Bh = smbuf + SPLITS * GA_SZ;      // [SPLITS][32][GB_PAD]

    const int tid = threadIdx.x;
    const int lane = tid & 31, w = tid >> 5;
    const int wm = w & 3, wn = w >> 2;
    const int row0 = blockIdx.y * 128, col0 = blockIdx.x * 128;

    float d[2][8][4];
    #pragma unroll
    for (int i = 0; i < 2; i++)
        #pragma unroll
        for (int j = 0; j < 8; j++)
            #pragma unroll
            for (int c = 0; c < 4; c++) d[i][j][c] = 0.0f;

    const int NC = (SPLITS == 3) ? 6 : 3;
    const int SA[6] = {0, 0, 1, 1, 0, 2};
    const int SB[6] = {0, 1, 0, 1, 2, 0};

    const int a_row = wm * 32 + (lane & 15);
    const int a_kof = (lane >> 4) << 3;
    const int b_kof = ((lane >> 3) & 1) * 8 + (lane & 7);
    const int b_nof = wn * 64 + (lane >> 4) * 8;

    for (int k0 = 0; k0 < K; k0 += 32) {
        #pragma unroll
        for (int it = 0; it < 4; it++) {
            int m = (tid >> 3) + it * 32;
            int kk = (tid & 7) * 4;
            float4 v4 = *(const float4*)(A + (size_t)(row0 + m) * K + k0 + kk);
            float r[4] = {v4.x, v4.y, v4.z, v4.w};
            __nv_bfloat16* dst = Ah + m * GA_PAD + kk;
            #pragma unroll
            for (int s = 0; s < SPLITS; s++) {
                __nv_bfloat16 b0 = __float2bfloat16(r[0]);
                __nv_bfloat16 b1 = __float2bfloat16(r[1]);
                __nv_bfloat16 b2 = __float2bfloat16(r[2]);
                __nv_bfloat16 b3 = __float2bfloat16(r[3]);
                if (s + 1 < SPLITS) {
                    r[0] -= __bfloat162float(b0); r[1] -= __bfloat162float(b1);
                    r[2] -= __bfloat162float(b2); r[3] -= __bfloat162float(b3);
                }
                __nv_bfloat162 p0; p0.x = b0; p0.y = b1;
                __nv_bfloat162 p1; p1.x = b2; p1.y = b3;
                *(__nv_bfloat162*)(dst + s * GA_SZ)     = p0;
                *(__nv_bfloat162*)(dst + s * GA_SZ + 2) = p1;
            }
        }
        #pragma unroll
        for (int it = 0; it < 4; it++) {
            int kk = (tid >> 5) + it * 8;
            int n  = (tid & 31) * 4;
            float4 v4 = *(const float4*)(B + (size_t)(k0 + kk) * N + col0 + n);
            float r[4] = {v4.x, v4.y, v4.z, v4.w};
            __nv_bfloat16* dst = Bh + kk * GB_PAD + n;
            #pragma unroll
            for (int s = 0; s < SPLITS; s++) {
                __nv_bfloat16 b0 = __float2bfloat16(r[0]);
                __nv_bfloat16 b1 = __float2bfloat16(r[1]);
                __nv_bfloat16 b2 = __float2bfloat16(r[2]);
                __nv_bfloat16 b3 = __float2bfloat16(r[3]);
                if (s + 1 < SPLITS) {
                    r[0] -= __bfloat162float(b0); r[1] -= __bfloat162float(b1);
                    r[2] -= __bfloat162float(b2); r[3] -= __bfloat162float(b3);
                }
                __nv_bfloat162 p0; p0.x = b0; p0.y = b1;
                __nv_bfloat162 p1; p1.x = b2; p1.y = b3;
                *(__nv_bfloat162*)(dst + s * GB_SZ)     = p0;
                *(__nv_bfloat162*)(dst + s * GB_SZ + 2) = p1;
            }
        }
        __syncthreads();

        #pragma unroll
        for (int kk = 0; kk < 32; kk += 16) {
            unsigned afr[3][2][4];
            #pragma unroll
            for (int s = 0; s < SPLITS; s++)
                #pragma unroll
                for (int mt = 0; mt < 2; mt++)
                    ldsm4(afr[s][mt],
                          Ah + s * GA_SZ + (a_row + mt * 16) * GA_PAD + kk + a_kof);
            #pragma unroll
            for (int nt4 = 0; nt4 < 4; nt4++) {
                unsigned bfr[3][4];
                #pragma unroll
                for (int s = 0; s < SPLITS; s++)
                    ldsm4t(bfr[s],
                           Bh + s * GB_SZ + (kk + b_kof) * GB_PAD + b_nof + nt4 * 16);
                #pragma unroll
                for (int mt = 0; mt < 2; mt++) {
                    #pragma unroll
                    for (int c = 0; c < NC; c++) {
                        mma16816(d[mt][nt4 * 2],     afr[SA[c]][mt], bfr[SB[c]][0], bfr[SB[c]][1]);
                        mma16816(d[mt][nt4 * 2 + 1], afr[SA[c]][mt], bfr[SB[c]][2], bfr[SB[c]][3]);
                    }
                }
            }
        }
        __syncthreads();
    }

    const int g = lane >> 2, l = lane & 3;
    #pragma unroll
    for (int mt = 0; mt < 2; mt++) {
        int r0 = row0 + wm * 32 + mt * 16 + g;
        #pragma unroll
        for (int nt = 0; nt < 8; nt++) {
            int c = col0 + wn * 64 + nt * 8 + 2 * l;
            float bia0 = bias[c], bia1 = bias[c + 1];
            float v0 = d[mt][nt][0] + bia0, v1 = d[mt][nt][1] + bia1;
            float v2 = d[mt][nt][2] + bia0, v3 = d[mt][nt][3] + bia1;
            if (ACT == 1) {
                v0 = gelu_exact(v0); v1 = gelu_exact(v1);
                v2 = gelu_exact(v2); v3 = gelu_exact(v3);
            }
            float2 p0 = {v0, v1}, p1 = {v2, v3};
            *(float2*)(C + (size_t)r0 * N + c) = p0;
            *(float2*)(C + (size_t)(r0 + 8) * N + c) = p1;
        }
    }
}

// ---------------- attention: scores[z,q,k] = 0.125 * q_h . k_h ----------------
__global__ void attn_scores(const float* __restrict__ q, const float* __restrict__ k,
                            float* __restrict__ sc) {
    int z = blockIdx.z, b = z / NH, h = z % NH;
    int k0 = blockIdx.x * 64, q0 = blockIdx.y * 64;
    __shared__ float qs[64][65];
    __shared__ float ks[64][65];
    int tid = threadIdx.x;
    int r = tid >> 2;
    int cbase = (tid & 3) * 16;
    const float* qp = q + (size_t)(b * SSZ + q0 + r) * DDIM + h * HD + cbase;
    const float* kp = k + (size_t)(b * SSZ + k0 + r) * DDIM + h * HD + cbase;
    #pragma unroll
    for (int u = 0; u < 4; u++) {
        float4 v4 = *(const float4*)(qp + u * 4);
        qs[cbase + u * 4 + 0][r] = v4.x; qs[cbase + u * 4 + 1][r] = v4.y;
        qs[cbase + u * 4 + 2][r] = v4.z; qs[cbase + u * 4 + 3][r] = v4.w;
        float4 w4 = *(const float4*)(kp + u * 4);
        ks[cbase + u * 4 + 0][r] = w4.x; ks[cbase + u * 4 + 1][r] = w4.y;
        ks[cbase + u * 4 + 2][r] = w4.z; ks[cbase + u * 4 + 3][r] = w4.w;
    }
    __syncthreads();
    int tx = tid & 15, ty = tid >> 4;
    float acc[4][4];
    #pragma unroll
    for (int i = 0; i < 4; i++)
        #pragma unroll
        for (int j = 0; j < 4; j++) acc[i][j] = 0.0f;
    #pragma unroll 8
    for (int kk = 0; kk < 64; kk++) {
        float a[4], bv[4];
        #pragma unroll
        for (int i = 0; i < 4; i++) a[i] = qs[kk][ty * 4 + i];
        #pragma unroll
        for (int j = 0; j < 4; j++) bv[j] = ks[kk][tx * 4 + j];
        #pragma unroll
        for (int i = 0; i < 4; i++)
            #pragma unroll
            for (int j = 0; j < 4; j++)
                acc[i][j] = fmaf(a[i], bv[j], acc[i][j]);
    }
    float* out = sc + (size_t)z * SSZ * SSZ;
    #pragma unroll
    for (int i = 0; i < 4; i++)
        #pragma unroll
        for (int j = 0; j < 4; j++)
            out[(size_t)(q0 + ty * 4 + i) * SSZ + k0 + tx * 4 + j] = acc[i][j] * 0.125f;
}

// ---------------- softmax over keys with per-(b,key) bias ----------------
__global__ void softmax_rows(float* __restrict__ sc, const float* __restrict__ kb) {
    int row = blockIdx.x;
    int b = row / (NH * SSZ);
    float* p = sc + (size_t)row * SSZ;
    const float* kbp = kb + b * SSZ;
    int tid = threadIdx.x;
    float v[4]; float mx = -3.4e38f;
    #pragma unroll
    for (int u = 0; u < 4; u++) {
        int c = u * 256 + tid;
        v[u] = p[c] + kbp[c];
        mx = fmaxf(mx, v[u]);
    }
    mx = blk_max(mx);
    float s = 0.0f;
    #pragma unroll
    for (int u = 0; u < 4; u++) { v[u] = expf(v[u] - mx); s += v[u]; }
    s = blk_sum(s);
    float inv = 1.0f / s;
    #pragma unroll
    for (int u = 0; u < 4; u++) p[u * 256 + tid] = v[u] * inv;
}

// ---------------- AV: attn[b,q,h*64+n] = probs[z] @ v_head ----------------
__global__ void attn_av(const float* __restrict__ sc, const float* __restrict__ v,
                        float* __restrict__ o) {
    int z = blockIdx.y, b = z / NH, h = z % NH;
    int q0 = blockIdx.x * 64;
    __shared__ float As[16][65];
    __shared__ float Bs[16][64];
    const float* Ab = sc + (size_t)z * SSZ * SSZ;
    const float* Vb = v + (size_t)b * SSZ * DDIM + h * HD;
    int tid = threadIdx.x;
    int ar = tid >> 2, ac = (tid & 3) * 4;
    int br = tid >> 4, bc = (tid & 15) * 4;
    int tx = tid & 15, ty = tid >> 4;
    float acc[4][4];
    #pragma unroll
    for (int i = 0; i < 4; i++)
        #pragma unroll
        for (int j = 0; j < 4; j++) acc[i][j] = 0.0f;
    for (int k0 = 0; k0 < SSZ; k0 += 16) {
        float4 a4 = *(const float4*)(Ab + (size_t)(q0 + ar) * SSZ + k0 + ac);
        As[ac + 0][ar] = a4.x; As[ac + 1][ar] = a4.y;
        As[ac + 2][ar] = a4.z; As[ac + 3][ar] = a4.w;
        float4 b4 = *(const float4*)(Vb + (size_t)(k0 + br) * DDIM + bc);
        *(float4*)&Bs[br][bc] = b4;
        __syncthreads();
        #pragma unroll
        for (int kk = 0; kk < 16; kk++) {
            float a[4], bf[4];
            #pragma unroll
            for (int i = 0; i < 4; i++) a[i] = As[kk][ty * 4 + i];
            #pragma unroll
            for (int j = 0; j < 4; j++) bf[j] = Bs[kk][tx * 4 + j];
            #pragma unroll
            for (int i = 0; i < 4; i++)
                #pragma unroll
                for (int j = 0; j < 4; j++)
                    acc[i][j] = fmaf(a[i], bf[j], acc[i][j]);
        }
        __syncthreads();
    }
    float* Ob = o + (size_t)(b * SSZ + q0) * DDIM + h * HD;
    #pragma unroll
    for (int i = 0; i < 4; i++)
        #pragma unroll
        for (int j = 0; j < 4; j++)
            Ob[(size_t)(ty * 4 + i) * DDIM + tx * 4 + j] = acc[i][j];
}

// ---------------- residual add + LayerNorm ----------------
__global__ void add_ln(const float* __restrict__ x, const float* __restrict__ y,
                       const float* __restrict__ g, const float* __restrict__ be,
                       float* __restrict__ out) {
    int row = blockIdx.x, tid = threadIdx.x;
    const float* xp = x + (size_t)row * DDIM;
    const float* yp = y + (size_t)row * DDIM;
    float v[4]; float s = 0.0f;
    #pragma unroll
    for (int u = 0; u < 4; u++) {
        int c = u * 256 + tid;
        v[u] = xp[c] + yp[c];
        s += v[u];
    }
    s = blk_sum(s);
    float mean = s * (1.0f / DDIM);
    float qv = 0.0f;
    #pragma unroll
    for (int u = 0; u < 4; u++) { float dd = v[u] - mean; qv += dd * dd; }
    qv = blk_sum(qv);
    float rstd = rsqrtf(qv * (1.0f / DDIM) + 1e-5f);
    float* op = out + (size_t)row * DDIM;
    #pragma unroll
    for (int u = 0; u < 4; u++) {
        int c = u * 256 + tid;
        op[c] = (v[u] - mean) * rstd * g[c] + be[c];
    }
}

// ---------------- importance score head ----------------
__global__ void score_head(const float* __restrict__ f, const float* __restrict__ Ws,
                           const float* __restrict__ bsc, const float* __restrict__ masks,
                           float* __restrict__ sv) {
    int row = blockIdx.x, tid = threadIdx.x;
    const float* fp = f + (size_t)row * DDIM;
    float s = 0.0f;
    #pragma unroll
    for (int u = 0; u < 4; u++) {
        int c = u * 256 + tid;
        s += fp[c] * Ws[c];
    }
    s = blk_sum(s);
    if (tid == 0) {
        float val = 1.0f / (1.0f + expf(-(s + bsc[0])));
        sv[row] = (masks[row] > 0.0f) ? val : 0.0f;
    }
}

__global__ void make_kb2(const float* __restrict__ masks, float* __restrict__ kb2) {
    int i = blockIdx.x * 256 + threadIdx.x;
    if (i < MTOT) kb2[i] = (masks[i] > 0.0f) ? 0.0f : -1e9f;
}

// ---------------- sequential scan per batch ----------------
__global__ void scan_kernel(const float* __restrict__ sv, const float* __restrict__ masks,
                            int* __restrict__ seg, float* __restrict__ mask_out) {
    int b = threadIdx.x;
    if (b >= BB) return;
    float c = 0.0f, maxseg = -1.0f;
    for (int t = 0; t < SSZ; t++) {
        c = c + sv[b * SSZ + t];
        float cf = floorf(c);
        int sg = (int)cf;
        if (sg > SSZ - 1) sg = SSZ - 1;
        if (sg < 0) sg = 0;
        seg[b * SSZ + t] = sg;
        if (masks[b * SSZ + t] > 0.0f) maxseg = fmaxf(maxseg, cf);
    }
    for (int t = 0; t < SSZ; t++)
        mask_out[b * SSZ + t] = ((float)t <= maxseg) ? 1.0f : 0.0f;
}

__global__ void zero_pool(float* __restrict__ p) {
    size_t i = (size_t)blockIdx.x * 256 + threadIdx.x;
    if (i < (size_t)MTOT * DDIM) p[i] = 0.0f;
}

__global__ void seg_pool(const float* __restrict__ x, const float* __restrict__ sv,
                         const int* __restrict__ seg, float* __restrict__ pooled) {
    int b = blockIdx.y;
    int dcol = blockIdx.x * 256 + threadIdx.x;
    __shared__ float svs[SSZ];
    __shared__ int sgs[SSZ];
    for (int t = threadIdx.x; t < SSZ; t += 256) {
        svs[t] = sv[b * SSZ + t];
        sgs[t] = seg[b * SSZ + t];
    }
    __syncthreads();
    const float* xb = x + (size_t)b * SSZ * DDIM + dcol;
    float acc = 0.0f;
    int cur = sgs[0];
    for (int t = 0; t < SSZ; t++) {
        int sg = sgs[t];
        if (sg != cur) {
            pooled[((size_t)b * SSZ + cur) * DDIM + dcol] = acc;
            acc = 0.0f;
            cur = sg;
        }
        acc = fmaf(xb[(size_t)t * DDIM], svs[t], acc);
    }
    pooled[((size_t)b * SSZ + cur) * DDIM + dcol] = acc;
}

// ---------------- host ----------------
extern "C" void kernel_launch(void* const* d_in, const int* in_sizes, int n_in,
                              void* d_out, int out_size) {
    const float* x     = (const float*)d_in[0];
    const float* masks = (const float*)d_in[1];
    const float* Wq = (const float*)d_in[2];  const float* bq = (const float*)d_in[3];
    const float* Wk = (const float*)d_in[4];  const float* bk = (const float*)d_in[5];
    const float* Wv = (const float*)d_in[6];  const float* bv = (const float*)d_in[7];
    const float* Wo = (const float*)d_in[8];  const float* bo = (const float*)d_in[9];
    const float* g1 = (const float*)d_in[10]; const float* be1 = (const float*)d_in[11];
    const float* g2 = (const float*)d_in[12]; const float* be2 = (const float*)d_in[13];
    const float* W1 = (const float*)d_in[14]; const float* bf1 = (const float*)d_in[15];
    const float* W2 = (const float*)d_in[16]; const float* bf2 = (const float*)d_in[17];
    const float* Ws = (const float*)d_in[18]; const float* bs = (const float*)d_in[19];
    const float* P1 = (const float*)d_in[20]; const float* bp1 = (const float*)d_in[21];
    const float* P2 = (const float*)d_in[22]; const float* bp2 = (const float*)d_in[23];
    float* out = (float*)d_out;

    float *q, *k, *v, *sc, *attn, *tmp, *h, *ffn, *feat, *feat2, *sv, *kb2, *pool, *ph;
    int* seg;
    cudaGetSymbolAddress((void**)&q, g_q);
    cudaGetSymbolAddress((void**)&k, g_k);
    cudaGetSymbolAddress((void**)&v, g_v);
    cudaGetSymbolAddress((void**)&sc, g_sc);
    cudaGetSymbolAddress((void**)&attn, g_attn);
    cudaGetSymbolAddress((void**)&tmp, g_tmp);
    cudaGetSymbolAddress((void**)&h, g_h);
    cudaGetSymbolAddress((void**)&ffn, g_ffn);
    cudaGetSymbolAddress((void**)&feat, g_feat);
    cudaGetSymbolAddress((void**)&feat2, g_feat2);
    cudaGetSymbolAddress((void**)&sv, g_sv);
    cudaGetSymbolAddress((void**)&kb2, g_kb2);
    cudaGetSymbolAddress((void**)&seg, g_seg);
    cudaGetSymbolAddress((void**)&pool, g_pool);
    cudaGetSymbolAddress((void**)&ph, g_ph);

    const int SM2 = 2 * (GA_SZ + GB_SZ) * 2;   // 37888 bytes
    cudaFuncSetAttribute(gemm_mma<2,0>, cudaFuncAttributeMaxDynamicSharedMemorySize, SM2);
    cudaFuncSetAttribute(gemm_mma<2,1>, cudaFuncAttributeMaxDynamicSharedMemorySize, SM2);

    dim3 gDD(DDIM / 128, MTOT / 128);

    auto layer = [&](const float* in, const float* kb, float* outf) {
        gemm128<0><<<gDD, 256>>>(in, Wq, bq, q, MTOT, DDIM, DDIM);
        gemm128<0><<<gDD, 256>>>(in, Wk, bk, k, MTOT, DDIM, DDIM);
        gemm128<0><<<gDD, 256>>>(in, Wv, bv, v, MTOT, DDIM, DDIM);
        dim3 gs(SSZ / 64, SSZ / 64, BB * NH);
        attn_scores<<<gs, 256>>>(q, k, sc);
        softmax_rows<<<BB * NH * SSZ, 256>>>(sc, kb);
        dim3 ga(SSZ / 64, BB * NH);
        attn_av<<<ga, 256>>>(sc, v, attn);
        gemm128<0><<<gDD, 256>>>(attn, Wo, bo, tmp, MTOT, DDIM, DDIM);
        add_ln<<<MTOT, 256>>>(in, tmp, g1, be1, h);
        gemm128<1><<<dim3(FF / 128, MTOT / 128), 256>>>(h, W1, bf1, ffn, MTOT, FF, DDIM);
        gemm128<0><<<gDD, 256>>>(ffn, W2, bf2, tmp, MTOT, DDIM, FF);
        add_ln<<<MTOT, 256>>>(h, tmp, g2, be2, outf);
    };

    layer(x, masks, feat);
    make_kb2<<<MTOT / 256, 256>>>(masks, kb2);
    layer(feat, kb2, feat2);

    score_head<<<MTOT, 256>>>(feat2, Ws, bs, masks, sv);
    scan_kernel<<<1, 32>>>(sv, masks, seg, out + (size_t)MTOT * HID);
    zero_pool<<<(MTOT * DDIM) / 256, 256>>>(pool);
    seg_pool<<<dim3(DDIM / 256, BB), 256>>>(x, sv, seg, pool);

    gemm_mma<2,1><<<dim3(HID / 128, MTOT / 128), 256, SM2>>>(pool, P1, bp1, ph, MTOT, HID, DDIM);
    gemm_mma<2,0><<<dim3(HID / 128, MTOT / 128), 256, SM2>>>(ph, P2, bp2, out, MTOT, HID, HID);
}